// round 11
// baseline (speedup 1.0000x reference)
#include <cuda_runtime.h>
#include <cuda_bf16.h>

#define N      512
#define DIM    256
#define EPSV   1e-12f
#define KLOG2E 14.426950408889634f   // SCAL(=10) * log2(e)

#define NBLK   128                   // all resident on 148 SMs -> spin safe
#define APITCH 68
#define BPITCH 36

__device__ float    g_D[N * N];
__device__ float    g_partial[NBLK];
__device__ float    g_pcount[NBLK];
__device__ unsigned g_stripe[16];    // per-row-stripe tile counters (target 16)
__device__ unsigned g_done = 0;

typedef unsigned long long ull;

__device__ __forceinline__ ull ffma2(ull a, ull b, ull c) {
    ull d; asm("fma.rn.f32x2 %0, %1, %2, %3;" : "=l"(d) : "l"(a), "l"(b), "l"(c));
    return d;
}
__device__ __forceinline__ ull addf2(ull a, ull b) {
    ull d; asm("add.rn.f32x2 %0, %1, %2;" : "=l"(d) : "l"(a), "l"(b));
    return d;
}
__device__ __forceinline__ void unpack2(ull v, float& lo, float& hi) {
    asm("mov.b64 {%0, %1}, %2;" : "=f"(lo), "=f"(hi) : "l"(v));
}
__device__ __forceinline__ float ex2a(float x) {
    float y; asm("ex2.approx.ftz.f32 %0, %1;" : "=f"(y) : "f"(x)); return y;
}
__device__ __forceinline__ float rcpa(float x) {
    float y; asm("rcp.approx.ftz.f32 %0, %1;" : "=f"(y) : "f"(x)); return y;
}
__device__ __forceinline__ unsigned ldacq(const unsigned* p) {
    unsigned v;
    asm volatile("ld.acquire.gpu.global.u32 %0, [%1];" : "=r"(v) : "l"(p) : "memory");
    return v;
}

// shared-memory pool offsets (phase 1 / phase 2 overlays)
#define OFF_AD   0            // float[4][16][68]  17408 B
#define OFF_BT   17408        // float[4][16][36]   9216 B
#define OFF_STG  26624        // ull  [3][128][4]  12288 B
#define OFF_SQI  38912        // float[32]
#define OFF_SQJ  39040        // float[32]
#define POOL_SZ  39424
// phase-2 overlay (after final phase-1 __syncthreads)
#define OFF_POSQ 0            // float[4][4][64]    4096 B
#define OFF_QCNT 4096         // int  [4][4]
#define OFF_QSAM 4160         // int  [4][4]
#define OFF_WACC 4224         // float[16]
#define OFF_RED  4288         // float[128]
#define OFF_LAST 4800         // int

__global__ void __launch_bounds__(512)
k_fused(const float* __restrict__ feat, const int* __restrict__ y,
        float* __restrict__ out) {
    __shared__ __align__(16) unsigned char pool[POOL_SZ];

    float (*Ad)[16][APITCH] = reinterpret_cast<float(*)[16][APITCH]>(pool + OFF_AD);
    float (*Bt)[16][BPITCH] = reinterpret_cast<float(*)[16][BPITCH]>(pool + OFF_BT);
    ull   (*stg)[128][4]    = reinterpret_cast<ull(*)[128][4]>(pool + OFF_STG);
    float* sqi = reinterpret_cast<float*>(pool + OFF_SQI);
    float* sqj = reinterpret_cast<float*>(pool + OFF_SQJ);

    const int tid  = threadIdx.x;
    const int bid  = blockIdx.x;
    const int warp = tid >> 5;
    const int lane = tid & 31;

    const float4* f4 = reinterpret_cast<const float4*>(feat);   // row pitch 64

    // =================== PHASE 1: triangle distance tiles ===================
    const int kq = tid >> 7;        // k-quarter 0..3
    const int r7 = tid & 127;
    const int ig = r7 & 15;
    const int jg = r7 >> 4;
    const int row = r7 >> 2;        // staging: row 0..31
    const int kf  = r7 & 3;         // staging: f4 slot

    int tlist[2];
    int ntl = 1;
    tlist[0] = bid;
    if (bid < 8) { tlist[0] = 128 + bid; tlist[1] = bid; ntl = 2; }

    for (int tt = 0; tt < ntl; ++tt) {
        const int tb = tlist[tt];
        int ti = (int)((sqrtf(8.f * tb + 1.f) - 1.f) * 0.5f);
        if ((ti + 1) * (ti + 2) / 2 <= tb) ++ti;
        if (ti * (ti + 1) / 2 > tb) --ti;
        const int tj = tb - ti * (ti + 1) / 2;
        const int i0 = ti * 32, j0 = tj * 32;

        __syncthreads();   // smem safe vs previous tile

        {   // squared norms: 64 rows, 8 threads/row
            const int r = tid >> 3, q = tid & 7;
            const int grow = (r < 32) ? (i0 + r) : (j0 + r - 32);
            float s = 0.f;
            #pragma unroll
            for (int u = 0; u < 8; ++u) {
                const float4 v = __ldg(&f4[grow * 64 + q * 8 + u]);
                s += v.x * v.x + v.y * v.y + v.z * v.z + v.w * v.w;
            }
            s += __shfl_xor_sync(0xffffffffu, s, 1);
            s += __shfl_xor_sync(0xffffffffu, s, 2);
            s += __shfl_xor_sync(0xffffffffu, s, 4);
            if (q == 0) { if (r < 32) sqi[r] = s; else sqj[r - 32] = s; }
        }

        ull acc00 = 0, acc01 = 0, acc10 = 0, acc11 = 0;

        float4 pfa = __ldg(&f4[(i0 + row) * 64 + kq * 16 + kf]);
        float4 pfb = __ldg(&f4[(j0 + row) * 64 + kq * 16 + kf]);

        for (int c = 0; c < 4; ++c) {            // 4 chunks of 16 k / quarter
            __syncthreads();
            {
                const float av[4] = {pfa.x, pfa.y, pfa.z, pfa.w};
                const float bv[4] = {pfb.x, pfb.y, pfb.z, pfb.w};
                #pragma unroll
                for (int e = 0; e < 4; ++e) {
                    Ad[kq][4 * kf + e][2 * row]     = av[e];
                    Ad[kq][4 * kf + e][2 * row + 1] = av[e];
                    Bt[kq][4 * kf + e][row]         = bv[e];
                }
            }
            __syncthreads();
            if (c < 3) {
                pfa = __ldg(&f4[(i0 + row) * 64 + kq * 16 + (c + 1) * 4 + kf]);
                pfb = __ldg(&f4[(j0 + row) * 64 + kq * 16 + (c + 1) * 4 + kf]);
            }
            const float* Ab = &Ad[kq][0][4 * ig];
            const float* Bb = &Bt[kq][0][4 * jg];
            #pragma unroll
            for (int k = 0; k < 16; ++k) {
                const ulonglong2 a = *reinterpret_cast<const ulonglong2*>(Ab + k * APITCH);
                const ulonglong2 b = *reinterpret_cast<const ulonglong2*>(Bb + k * BPITCH);
                acc00 = ffma2(a.x, b.x, acc00);
                acc01 = ffma2(a.x, b.y, acc01);
                acc10 = ffma2(a.y, b.x, acc10);
                acc11 = ffma2(a.y, b.y, acc11);
            }
        }

        __syncthreads();
        if (kq >= 1) {
            stg[kq - 1][r7][0] = acc00; stg[kq - 1][r7][1] = acc01;
            stg[kq - 1][r7][2] = acc10; stg[kq - 1][r7][3] = acc11;
        }
        __syncthreads();
        if (kq == 0) {
            #pragma unroll
            for (int s = 0; s < 3; ++s) {
                acc00 = addf2(acc00, stg[s][r7][0]);
                acc01 = addf2(acc01, stg[s][r7][1]);
                acc10 = addf2(acc10, stg[s][r7][2]);
                acc11 = addf2(acc11, stg[s][r7][3]);
            }
            float d[2][4];
            unpack2(acc00, d[0][0], d[0][1]); unpack2(acc01, d[0][2], d[0][3]);
            unpack2(acc10, d[1][0], d[1][1]); unpack2(acc11, d[1][2], d[1][3]);
            #pragma unroll
            for (int rr = 0; rr < 2; ++rr) {
                const int   orow = 2 * ig + rr;
                const float si   = sqi[orow];
                float o[4];
                #pragma unroll
                for (int cc = 0; cc < 4; ++cc)
                    o[cc] = sqrtf(fmaxf(si + sqj[4 * jg + cc] - 2.f * d[rr][cc], EPSV));
                *reinterpret_cast<float4*>(&g_D[(i0 + orow) * N + j0 + 4 * jg]) =
                    make_float4(o[0], o[1], o[2], o[3]);
                if (ti != tj) {
                    #pragma unroll
                    for (int cc = 0; cc < 4; ++cc)
                        g_D[(j0 + 4 * jg + cc) * N + i0 + orow] = o[cc];
                }
            }
        }
        __threadfence();
        __syncthreads();
        if (tid == 0) {
            atomicAdd(&g_stripe[ti], 1u);
            if (ti != tj) atomicAdd(&g_stripe[tj], 1u);
        }
    }

    // =================== wait for this block's anchor stripe ===================
    if (tid == 0) {
        const unsigned* ctr = &g_stripe[bid >> 3];
        while (ldacq(ctr) < 16u) { }
    }
    __syncthreads();          // also fences phase-1 smem before overlay reuse

    // =================== PHASE 2: 4 anchors, 4 warps each ===================
    float (*posQ)[4][64] = reinterpret_cast<float(*)[4][64]>(pool + OFF_POSQ);
    int*   qcnt  = reinterpret_cast<int*>(pool + OFF_QCNT);
    int*   qsame = reinterpret_cast<int*>(pool + OFF_QSAM);
    float* wacc  = reinterpret_cast<float*>(pool + OFF_WACC);
    float* red   = reinterpret_cast<float*>(pool + OFF_RED);
    int*   lastp = reinterpret_cast<int*>(pool + OFF_LAST);

    const int   wa   = warp >> 2;                 // anchor slot 0..3
    const int   sub  = warp & 3;                  // column quarter
    const int   a    = bid * 4 + wa;
    const float INF  = __int_as_float(0x7f800000);

    const int   ya   = __ldg(&y[a]);
    const float cref = __ldcg(&g_D[a * N + ((a + 1) & (N - 1))]) * KLOG2E;

    const int idx = 128 * sub + 4 * lane;
    const int4   yv = *reinterpret_cast<const int4*>(y + idx);
    const float4 xv = __ldcg(reinterpret_cast<const float4*>(&g_D[a * N + idx]));
    const int   yl[4] = {yv.x, yv.y, yv.z, yv.w};
    const float xa[4] = {xv.x * KLOG2E, xv.y * KLOG2E, xv.z * KLOG2E, xv.w * KLOG2E};

    int cnt = 0, same = 0;
    #pragma unroll
    for (int i = 0; i < 4; ++i) {
        const int  j  = idx + i;
        const bool sc = (yl[i] == ya);
        const bool v  = sc && (j != a);
        const unsigned ms = __ballot_sync(0xffffffffu, sc);
        const unsigned mv = __ballot_sync(0xffffffffu, v);
        if (v) {
            const int slot = cnt + __popc(mv & ((1u << lane) - 1u));
            posQ[wa][sub][slot] = fminf(fmaxf(ex2a(cref - xa[i]), 1e-30f), 1e30f);
        }
        cnt  += __popc(mv);
        same += __popc(ms);
    }
    if (lane == 0) { qcnt[wa * 4 + sub] = cnt; qsame[wa * 4 + sub] = same; }

    float ex[4];
    #pragma unroll
    for (int i = 0; i < 4; ++i)
        ex[i] = (yl[i] == ya) ? INF : fmaxf(ex2a(xa[i] - cref), 1e-30f);

    __syncthreads();

    float ac0 = 0.f, ac1 = 0.f, ac2 = 0.f, ac3 = 0.f;
    #pragma unroll
    for (int q = 0; q < 4; ++q) {
        const int c = qcnt[wa * 4 + q];
        const float* pl = posQ[wa][q];
        for (int p = 0; p < c; ++p) {
            const float rp = pl[p];
            ac0 += rcpa(fmaf(ex[0], rp, 1.f));
            ac1 += rcpa(fmaf(ex[1], rp, 1.f));
            ac2 += rcpa(fmaf(ex[2], rp, 1.f));
            ac3 += rcpa(fmaf(ex[3], rp, 1.f));
        }
    }
    float acc = (ac0 + ac1) + (ac2 + ac3);
    #pragma unroll
    for (int o = 16; o > 0; o >>= 1) acc += __shfl_xor_sync(0xffffffffu, acc, o);
    if (lane == 0) wacc[warp] = acc;
    __syncthreads();

    if (tid == 0) {
        float s = 0.f;
        #pragma unroll
        for (int w = 0; w < 16; ++w) s += wacc[w];
        float cc = 0.f;
        #pragma unroll
        for (int q = 0; q < 4; ++q) {
            const int np = qcnt[q*4+0] + qcnt[q*4+1] + qcnt[q*4+2] + qcnt[q*4+3];
            const int sm = qsame[q*4+0] + qsame[q*4+1] + qsame[q*4+2] + qsame[q*4+3];
            cc += (float)(np * (N - sm));
        }
        g_partial[bid] = s;
        g_pcount[bid]  = cc;
        __threadfence();
        const unsigned t = atomicAdd(&g_done, 1u);
        *lastp = (t == NBLK - 1);
    }
    __syncthreads();

    // =================== FINAL REDUCE (last block) ===================
    if (*lastp) {
        __threadfence();
        if (tid < NBLK) red[tid] = __ldcg(&g_partial[tid]);
        __syncthreads();
        #pragma unroll
        for (int st = 64; st > 0; st >>= 1) {
            if (tid < st) red[tid] += red[tid + st];
            __syncthreads();
        }
        const float tot = red[0];
        __syncthreads();
        if (tid < NBLK) red[tid] = __ldcg(&g_pcount[tid]);
        __syncthreads();
        #pragma unroll
        for (int st = 64; st > 0; st >>= 1) {
            if (tid < st) red[tid] += red[tid + st];
            __syncthreads();
        }
        if (tid == 0) {
            out[0] = tot / red[0];
            g_done = 0;                           // reset for next graph replay
        }
        if (tid < 16) g_stripe[tid] = 0;
    }
}

// ---------------------------------------------------------------------------
extern "C" void kernel_launch(void* const* d_in, const int* in_sizes, int n_in,
                              void* d_out, int out_size) {
    const float* feat = (const float*)d_in[0];
    // d_in[1] = logits (unused by the loss)
    const int*   y    = (const int*)d_in[2];
    float*       out  = (float*)d_out;

    k_fused<<<NBLK, 512>>>(feat, y, out);
}

// round 12
// speedup vs baseline: 1.4691x; 1.4691x over previous
#include <cuda_runtime.h>
#include <cuda_bf16.h>

#define N      512
#define DIM    256
#define EPSV   1e-12f
#define KLOG2E 14.426950408889634f   // SCAL(=10) * log2(e)

#define NTRI   136                   // 16*17/2 triangular 32x32 tiles
#define TBLK   256                   // triplet blocks (2 anchors each)
#define APITCH 68
#define BPITCH 36

__device__ float    g_D[N * N];
__device__ float    g_partial[TBLK];
__device__ float    g_pcount[TBLK];
__device__ unsigned g_done = 0;

typedef unsigned long long ull;

__device__ __forceinline__ ull ffma2(ull a, ull b, ull c) {
    ull d; asm("fma.rn.f32x2 %0, %1, %2, %3;" : "=l"(d) : "l"(a), "l"(b), "l"(c));
    return d;
}
__device__ __forceinline__ ull addf2(ull a, ull b) {
    ull d; asm("add.rn.f32x2 %0, %1, %2;" : "=l"(d) : "l"(a), "l"(b));
    return d;
}
__device__ __forceinline__ void unpack2(ull v, float& lo, float& hi) {
    asm("mov.b64 {%0, %1}, %2;" : "=f"(lo), "=f"(hi) : "l"(v));
}
__device__ __forceinline__ float ex2a(float x) {
    float y; asm("ex2.approx.ftz.f32 %0, %1;" : "=f"(y) : "f"(x)); return y;
}
__device__ __forceinline__ float rcpa(float x) {
    float y; asm("rcp.approx.ftz.f32 %0, %1;" : "=f"(y) : "f"(x)); return y;
}

// ---------------------------------------------------------------------------
// Kernel 1 (R9, proven): lower-triangle 32x32 distance tiles, f32x2 FMA.
// ---------------------------------------------------------------------------
__global__ void __launch_bounds__(512)
k_dist(const float* __restrict__ feat) {
    __shared__ __align__(16) float Ad[4][16][APITCH];
    __shared__ __align__(16) float Bt[4][16][BPITCH];
    __shared__ float sqi[32], sqj[32];
    __shared__ ull   stg[3][128][4];

    const int tid = threadIdx.x;
    const int bid = blockIdx.x;

    int ti = (int)((sqrtf(8.f * bid + 1.f) - 1.f) * 0.5f);
    if ((ti + 1) * (ti + 2) / 2 <= bid) ++ti;
    if (ti * (ti + 1) / 2 > bid) --ti;
    const int tj = bid - ti * (ti + 1) / 2;
    const int i0 = ti * 32, j0 = tj * 32;

    const float4* f4 = reinterpret_cast<const float4*>(feat);

    {   // squared norms: 64 rows, 8 threads/row
        const int r = tid >> 3, q = tid & 7;
        const int grow = (r < 32) ? (i0 + r) : (j0 + r - 32);
        float s = 0.f;
        #pragma unroll
        for (int u = 0; u < 8; ++u) {
            const float4 v = __ldg(&f4[grow * 64 + q * 8 + u]);
            s += v.x * v.x + v.y * v.y + v.z * v.z + v.w * v.w;
        }
        s += __shfl_xor_sync(0xffffffffu, s, 1);
        s += __shfl_xor_sync(0xffffffffu, s, 2);
        s += __shfl_xor_sync(0xffffffffu, s, 4);
        if (q == 0) { if (r < 32) sqi[r] = s; else sqj[r - 32] = s; }
    }

    const int kq = tid >> 7;
    const int r7 = tid & 127;
    const int ig = r7 & 15;
    const int jg = r7 >> 4;
    const int row = r7 >> 2;
    const int kf  = r7 & 3;

    ull acc00 = 0, acc01 = 0, acc10 = 0, acc11 = 0;

    float4 pfa = __ldg(&f4[(i0 + row) * 64 + kq * 16 + kf]);
    float4 pfb = __ldg(&f4[(j0 + row) * 64 + kq * 16 + kf]);

    for (int c = 0; c < 4; ++c) {
        __syncthreads();
        {
            const float av[4] = {pfa.x, pfa.y, pfa.z, pfa.w};
            const float bv[4] = {pfb.x, pfb.y, pfb.z, pfb.w};
            #pragma unroll
            for (int e = 0; e < 4; ++e) {
                Ad[kq][4 * kf + e][2 * row]     = av[e];
                Ad[kq][4 * kf + e][2 * row + 1] = av[e];
                Bt[kq][4 * kf + e][row]         = bv[e];
            }
        }
        __syncthreads();
        if (c < 3) {
            pfa = __ldg(&f4[(i0 + row) * 64 + kq * 16 + (c + 1) * 4 + kf]);
            pfb = __ldg(&f4[(j0 + row) * 64 + kq * 16 + (c + 1) * 4 + kf]);
        }
        const float* Ab = &Ad[kq][0][4 * ig];
        const float* Bb = &Bt[kq][0][4 * jg];
        #pragma unroll
        for (int k = 0; k < 16; ++k) {
            const ulonglong2 a = *reinterpret_cast<const ulonglong2*>(Ab + k * APITCH);
            const ulonglong2 b = *reinterpret_cast<const ulonglong2*>(Bb + k * BPITCH);
            acc00 = ffma2(a.x, b.x, acc00);
            acc01 = ffma2(a.x, b.y, acc01);
            acc10 = ffma2(a.y, b.x, acc10);
            acc11 = ffma2(a.y, b.y, acc11);
        }
    }

    __syncthreads();
    if (kq >= 1) {
        stg[kq - 1][r7][0] = acc00; stg[kq - 1][r7][1] = acc01;
        stg[kq - 1][r7][2] = acc10; stg[kq - 1][r7][3] = acc11;
    }
    __syncthreads();
    if (kq == 0) {
        #pragma unroll
        for (int s = 0; s < 3; ++s) {
            acc00 = addf2(acc00, stg[s][r7][0]);
            acc01 = addf2(acc01, stg[s][r7][1]);
            acc10 = addf2(acc10, stg[s][r7][2]);
            acc11 = addf2(acc11, stg[s][r7][3]);
        }
        float d[2][4];
        unpack2(acc00, d[0][0], d[0][1]); unpack2(acc01, d[0][2], d[0][3]);
        unpack2(acc10, d[1][0], d[1][1]); unpack2(acc11, d[1][2], d[1][3]);
        #pragma unroll
        for (int rr = 0; rr < 2; ++rr) {
            const int   orow = 2 * ig + rr;
            const float si   = sqi[orow];
            float o[4];
            #pragma unroll
            for (int cc = 0; cc < 4; ++cc)
                o[cc] = sqrtf(fmaxf(si + sqj[4 * jg + cc] - 2.f * d[rr][cc], EPSV));
            *reinterpret_cast<float4*>(&g_D[(i0 + orow) * N + j0 + 4 * jg]) =
                make_float4(o[0], o[1], o[2], o[3]);
            if (ti != tj) {
                #pragma unroll
                for (int cc = 0; cc < 4; ++cc)
                    g_D[(j0 + 4 * jg + cc) * N + i0 + orow] = o[cc];
            }
        }
    }
}

// ---------------------------------------------------------------------------
// Kernel 2: triplet sums, 256 blocks x 256 threads, 2 anchors/block,
// 4 warps per anchor (each warp owns a 128-column region). Deterministic
// per-region positive lists; single-warp shuffle tail reduce.
// ---------------------------------------------------------------------------
__global__ void __launch_bounds__(256)
k_triplet(const int* __restrict__ y, float* __restrict__ out) {
    __shared__ float posR[2][4][48];
    __shared__ int   qcnt[2][4], qsame[2][4];
    __shared__ float wacc[8];
    __shared__ int   last_s;

    const int tid  = threadIdx.x;
    const int bid  = blockIdx.x;
    const int warp = tid >> 5;
    const int lane = tid & 31;
    const int q    = warp >> 2;          // anchor slot 0/1
    const int r    = warp & 3;           // column region 0..3
    const int a    = bid * 2 + q;
    const float INF = __int_as_float(0x7f800000);

    const int   ya   = __ldg(&y[a]);
    const float cref = __ldcg(&g_D[a * N + ((a + 1) & (N - 1))]) * KLOG2E;

    const int idx = 128 * r + 4 * lane;
    const int4   yv = *reinterpret_cast<const int4*>(y + idx);
    const float4 xv = __ldcg(reinterpret_cast<const float4*>(&g_D[a * N + idx]));
    const int   yl[4] = {yv.x, yv.y, yv.z, yv.w};
    const float xa[4] = {xv.x * KLOG2E, xv.y * KLOG2E, xv.z * KLOG2E, xv.w * KLOG2E};

    // warp-cooperative scan of this 128-column region (4 ballot rounds)
    int cnt = 0, same = 0;
    #pragma unroll
    for (int i = 0; i < 4; ++i) {
        const int  j  = idx + i;
        const bool sc = (yl[i] == ya);
        const bool v  = sc && (j != a);
        const unsigned ms = __ballot_sync(0xffffffffu, sc);
        const unsigned mv = __ballot_sync(0xffffffffu, v);
        if (v) {
            const int slot = cnt + __popc(mv & ((1u << lane) - 1u));
            if (slot < 48)
                posR[q][r][slot] = fminf(fmaxf(ex2a(cref - xa[i]), 1e-30f), 1e30f);
        }
        cnt  += __popc(mv);
        same += __popc(ms);
    }
    if (lane == 0) { qcnt[q][r] = (cnt < 48) ? cnt : 48; qsame[q][r] = same; }

    float ex[4];
    #pragma unroll
    for (int i = 0; i < 4; ++i)
        ex[i] = (yl[i] == ya) ? INF : fmaxf(ex2a(xa[i] - cref), 1e-30f);

    __syncthreads();

    // sigmoid sums: all positives of anchor q against this lane's 4 negatives
    float ac0 = 0.f, ac1 = 0.f, ac2 = 0.f, ac3 = 0.f;
    #pragma unroll
    for (int r2 = 0; r2 < 4; ++r2) {
        const int    c  = qcnt[q][r2];
        const float* pl = posR[q][r2];
        for (int p = 0; p < c; ++p) {
            const float rp = pl[p];
            ac0 += rcpa(fmaf(ex[0], rp, 1.f));
            ac1 += rcpa(fmaf(ex[1], rp, 1.f));
            ac2 += rcpa(fmaf(ex[2], rp, 1.f));
            ac3 += rcpa(fmaf(ex[3], rp, 1.f));
        }
    }
    float acc = (ac0 + ac1) + (ac2 + ac3);
    #pragma unroll
    for (int o = 16; o > 0; o >>= 1) acc += __shfl_xor_sync(0xffffffffu, acc, o);
    if (lane == 0) wacc[warp] = acc;
    __syncthreads();

    if (tid == 0) {
        float s = 0.f;
        #pragma unroll
        for (int w = 0; w < 8; ++w) s += wacc[w];
        const int np0 = qcnt[0][0] + qcnt[0][1] + qcnt[0][2] + qcnt[0][3];
        const int sm0 = qsame[0][0] + qsame[0][1] + qsame[0][2] + qsame[0][3];
        const int np1 = qcnt[1][0] + qcnt[1][1] + qcnt[1][2] + qcnt[1][3];
        const int sm1 = qsame[1][0] + qsame[1][1] + qsame[1][2] + qsame[1][3];
        g_partial[bid] = s;
        g_pcount[bid]  = (float)(np0 * (N - sm0) + np1 * (N - sm1));
        __threadfence();
        const unsigned t = atomicAdd(&g_done, 1u);
        last_s = (t == TBLK - 1);
    }
    __syncthreads();

    // single-warp tail reduce (no barriers): 256 partials = 8 per lane
    if (last_s && warp == 0) {
        __threadfence();
        const float4* p4 = reinterpret_cast<const float4*>(g_partial);
        const float4* c4 = reinterpret_cast<const float4*>(g_pcount);
        const float4 s0 = __ldcg(&p4[2 * lane]);
        const float4 s1 = __ldcg(&p4[2 * lane + 1]);
        const float4 n0 = __ldcg(&c4[2 * lane]);
        const float4 n1 = __ldcg(&c4[2 * lane + 1]);
        float s = ((s0.x + s0.y) + (s0.z + s0.w)) + ((s1.x + s1.y) + (s1.z + s1.w));
        float n = ((n0.x + n0.y) + (n0.z + n0.w)) + ((n1.x + n1.y) + (n1.z + n1.w));
        #pragma unroll
        for (int o = 16; o > 0; o >>= 1) {
            s += __shfl_xor_sync(0xffffffffu, s, o);
            n += __shfl_xor_sync(0xffffffffu, n, o);
        }
        if (lane == 0) {
            out[0] = s / n;
            g_done = 0;                   // reset for next graph replay
        }
    }
}

// ---------------------------------------------------------------------------
extern "C" void kernel_launch(void* const* d_in, const int* in_sizes, int n_in,
                              void* d_out, int out_size) {
    const float* feat = (const float*)d_in[0];
    // d_in[1] = logits (unused by the loss)
    const int*   y    = (const int*)d_in[2];
    float*       out  = (float*)d_out;

    k_dist   <<<NTRI, 512>>>(feat);
    k_triplet<<<TBLK, 256>>>(y, out);
}